// round 7
// baseline (speedup 1.0000x reference)
#include <cuda_runtime.h>
#include <cstdint>

// Problem constants
#define N_ROWS 8192
#define D_DIM  64
#define B_HALF 1024          // epsilon = [tmp; -tmp] antisymmetry folds B=2048 -> 1024
#define TWO_PI 6.283185307179586f

// Tiling
#define TB      256          // threads per block
#define ROWS_T  128          // rows per block (64 rowpairs)
#define BT      64           // basis per block
#define NG      (B_HALF / BT)   // 16 b-groups

typedef unsigned long long u64;

// Shared layout (u64 strides, padded to skew banks; even -> 16B alignment holds)
#define SX_STRIDE 66         // u64 per k-row of x tile (64 rowpairs + pad)
#define SS_STRIDE 66         // u64 per k-row of s tile (64 splatted basis + pad)
#define SM_STRIDE 66         // u64 per b-row of M tile (64 splatted dims + pad)
#define SU_STRIDE 66         // u64 per b-row of U tile (64 rowpairs + pad)  [R6 fix: was 34]
#define OFF_X  0
#define OFF_S  (64 * SX_STRIDE * 8)                 // 33792
#define OFF_W  (OFF_S + 64 * SS_STRIDE * 8)         // 67584
#define SMEM_BYTES (OFF_W + 3 * 64 * 4)             // + ws/wc/rlam = 68352

// Packed f32x2 math (Blackwell FFMA2 — full-rate fp32, 2 FMAs per instruction)
#define FMA2(d, a, b, c) asm("fma.rn.f32x2 %0, %1, %2, %3;" : "=l"(d) : "l"(a), "l"(b), "l"(c))
#define MUL2(d, a, b)    asm("mul.rn.f32x2 %0, %1, %2;"     : "=l"(d) : "l"(a), "l"(b))
#define PACK2(d, lo, hi) asm("mov.b64 %0, {%1, %2};"        : "=l"(d) : "f"(lo), "f"(hi))
#define UNPACK2(lo, hi, s) asm("mov.b64 {%0, %1}, %2;"      : "=f"(lo), "=f"(hi) : "l"(s))

// Device scratch
__device__ float g_part[NG * N_ROWS * D_DIM];   // 32 MB partials

// ---------------------------------------------------------------------------
// Fused kernel: in-block prep + register-tiled GEMM A (sim) + sincos +
// register-tiled GEMM B (U @ M). Operand tiles stored pre-splatted (u64,
// both lanes equal) so the inner loops are pure LDS.128 + FFMA2.
// Thread (ty = tid/16, tx = tid%16):
//   Phase A: 8 rows (rowpairs rp = 4ty..+3) x 4 basis (b = 4tx..+3)
//   Phase B: 8 rows x 4 dims (d = 4tx..+3), K = 64 basis of this group
// ---------------------------------------------------------------------------
__global__ void __launch_bounds__(TB, 2)
main_kernel(const float* __restrict__ x,
            const float* __restrict__ eps,
            const float* __restrict__ lam,
            const float* __restrict__ eta,
            const float* __restrict__ w) {
    extern __shared__ char smem[];
    u64*   sX2 = (u64*)(smem + OFF_X);     // [64 k][SX_STRIDE]  x rowpairs
    u64*   sS2 = (u64*)(smem + OFF_S);     // [64 k][SS_STRIDE]  s splatted
    float* sWs = (float*)(smem + OFF_W);   // [64]
    float* sWc = sWs + 64;                 // [64]
    float* sRl = sWc + 64;                 // [64] 1/(2*pi*lam)
    u64*   sM2 = (u64*)(smem + OFF_X);     // alias: [64 b][SM_STRIDE] M splatted
    u64*   sU2 = (u64*)(smem + OFF_S);     // alias: [64 b][SU_STRIDE] U rowpairs

    const int tid = threadIdx.x;
    const int ty  = tid >> 4;              // 0..15
    const int tx  = tid & 15;              // 0..15
    const int bx  = blockIdx.x;
    const int g   = blockIdx.y;
    const int b0  = g * BT;

    // ---- Stage 0: rlam + effective weights ----
    if (tid < 64) {
        sRl[tid] = 1.0f / (TWO_PI * lam[tid]);
    } else if (tid < 128) {
        int b = tid - 64;
        sWs[b] = -(w[b0 + b] + w[b0 + b + B_HALF]);
    } else if (tid < 192) {
        int b = tid - 128;
        sWc[b] = w[2 * B_HALF + b0 + b] - w[3 * B_HALF + b0 + b];
    }
    __syncthreads();

    // ---- Stage 1: x tile transposed (rowpair-packed) + S tile (splatted) ----
    {
        float* sXf = (float*)sX2;
        const float4* xg = (const float4*)(x + (size_t)bx * ROWS_T * D_DIM);
        #pragma unroll
        for (int it = 0; it < 8; ++it) {
            int i  = tid + it * TB;        // float4 id, 2048 total
            int r  = i >> 4;
            int k4 = (i & 15) * 4;
            float4 v = xg[i];
            sXf[(k4 + 0) * (2 * SX_STRIDE) + r] = v.x;
            sXf[(k4 + 1) * (2 * SX_STRIDE) + r] = v.y;
            sXf[(k4 + 2) * (2 * SX_STRIDE) + r] = v.z;
            sXf[(k4 + 3) * (2 * SX_STRIDE) + r] = v.w;
        }
        const float4* eg = (const float4*)(eps + (size_t)b0 * D_DIM);
        const float4* rl4 = (const float4*)sRl;
        #pragma unroll
        for (int it = 0; it < 4; ++it) {
            int i  = tid + it * TB;        // float4 id, 1024 total
            int b  = i >> 4;
            int k4 = (i & 15) * 4;
            float4 e = eg[i];
            float4 r = rl4[i & 15];
            float s0 = e.x * r.x, s1 = e.y * r.y, s2 = e.z * r.z, s3 = e.w * r.w;
            u64 v0, v1, v2, v3;
            PACK2(v0, s0, s0);
            PACK2(v1, s1, s1);
            PACK2(v2, s2, s2);
            PACK2(v3, s3, s3);
            sS2[(k4 + 0) * SS_STRIDE + b] = v0;
            sS2[(k4 + 1) * SS_STRIDE + b] = v1;
            sS2[(k4 + 2) * SS_STRIDE + b] = v2;
            sS2[(k4 + 3) * SS_STRIDE + b] = v3;
        }
    }
    __syncthreads();

    // ---- Phase A: sim tile. acc[i=b_local][j=rowpair] ----
    u64 acc[4][4];
    #pragma unroll
    for (int i = 0; i < 4; ++i)
        #pragma unroll
        for (int j = 0; j < 4; ++j) acc[i][j] = 0ull;

    {
        const u64* xb = sX2 + 4 * ty;
        const u64* sb = sS2 + 4 * tx;
        #pragma unroll 2
        for (int k = 0; k < 64; ++k) {
            ulonglong2 xa = *(const ulonglong2*)(xb + k * SX_STRIDE);
            ulonglong2 xc = *(const ulonglong2*)(xb + k * SX_STRIDE + 2);
            ulonglong2 sa = *(const ulonglong2*)(sb + k * SS_STRIDE);
            ulonglong2 sc = *(const ulonglong2*)(sb + k * SS_STRIDE + 2);
            u64 xv0 = xa.x, xv1 = xa.y, xv2 = xc.x, xv3 = xc.y;
            u64 s0 = sa.x, s1 = sa.y, s2 = sc.x, s3 = sc.y;
            FMA2(acc[0][0], xv0, s0, acc[0][0]);
            FMA2(acc[0][1], xv1, s0, acc[0][1]);
            FMA2(acc[0][2], xv2, s0, acc[0][2]);
            FMA2(acc[0][3], xv3, s0, acc[0][3]);
            FMA2(acc[1][0], xv0, s1, acc[1][0]);
            FMA2(acc[1][1], xv1, s1, acc[1][1]);
            FMA2(acc[1][2], xv2, s1, acc[1][2]);
            FMA2(acc[1][3], xv3, s1, acc[1][3]);
            FMA2(acc[2][0], xv0, s2, acc[2][0]);
            FMA2(acc[2][1], xv1, s2, acc[2][1]);
            FMA2(acc[2][2], xv2, s2, acc[2][2]);
            FMA2(acc[2][3], xv3, s2, acc[2][3]);
            FMA2(acc[3][0], xv0, s3, acc[3][0]);
            FMA2(acc[3][1], xv1, s3, acc[3][1]);
            FMA2(acc[3][2], xv2, s3, acc[3][2]);
            FMA2(acc[3][3], xv3, s3, acc[3][3]);
        }
    }

    // ---- Epilogue: acc (sim/2pi) -> u = sin*ws + cos*wc, in registers ----
    #pragma unroll
    for (int i = 0; i < 4; ++i) {
        int bl = tx * 4 + i;
        float ws = sWs[bl];
        float wc = sWc[bl];
        #pragma unroll
        for (int j = 0; j < 4; ++j) {
            float p0, p1;
            UNPACK2(p0, p1, acc[i][j]);
            float r0 = p0 - rintf(p0);
            float r1 = p1 - rintf(p1);
            float t0 = r0 * TWO_PI;
            float t1 = r1 * TWO_PI;
            float u0 = __sinf(t0) * ws + __cosf(t0) * wc;
            float u1 = __sinf(t1) * ws + __cosf(t1) * wc;
            PACK2(acc[i][j], u0, u1);
        }
    }

    __syncthreads();   // everyone done reading x-region (and s-region phase A)

    // ---- Stage 2: derive splatted M tile from splatted S tile.
    //      M[b][d<32]  =  2pi * S[b][32+d]
    //      M[b][d>=32] = -2pi * S[b][d-32] - 2pi*eta^2 * S[b][d]
    //      S[b][j] lives (splatted) at sS2[j*SS_STRIDE + b].
    {
        float e  = eta[0];
        float c1 = -TWO_PI * e * e;   // coeff on S[b][d]
        u64 pos2, neg2, c12;
        PACK2(pos2, TWO_PI, TWO_PI);
        PACK2(neg2, -TWO_PI, -TWO_PI);
        PACK2(c12, c1, c1);
        #pragma unroll
        for (int it = 0; it < 16; ++it) {
            int i = tid + it * TB;         // 4096 total
            int b = i >> 6;
            int d = i & 63;
            u64 m;
            if (d < 32) {
                u64 sv = sS2[(32 + d) * SS_STRIDE + b];
                MUL2(m, sv, pos2);
            } else {
                u64 s1 = sS2[(d - 32) * SS_STRIDE + b];
                u64 s2 = sS2[d * SS_STRIDE + b];
                u64 t;
                MUL2(t, s2, c12);
                FMA2(m, s1, neg2, t);
            }
            sM2[b * SM_STRIDE + d] = m;
        }
    }
    __syncthreads();   // everyone done reading s-region

    // ---- Stage 3: write U tile (rowpair-packed) into s-region ----
    #pragma unroll
    for (int i = 0; i < 4; ++i) {
        int bl = tx * 4 + i;
        #pragma unroll
        for (int j = 0; j < 4; ++j) {
            sU2[bl * SU_STRIDE + ty * 4 + j] = acc[i][j];
        }
    }
    __syncthreads();

    // ---- Phase B: f_partial = U @ M.  o[j=rowpair][i=d_local] ----
    u64 o[4][4];
    #pragma unroll
    for (int j = 0; j < 4; ++j)
        #pragma unroll
        for (int i = 0; i < 4; ++i) o[j][i] = 0ull;

    {
        const u64* ub = sU2 + 4 * ty;
        const u64* mb = sM2 + 4 * tx;
        #pragma unroll 2
        for (int b = 0; b < 64; ++b) {
            ulonglong2 ua = *(const ulonglong2*)(ub + b * SU_STRIDE);
            ulonglong2 uc = *(const ulonglong2*)(ub + b * SU_STRIDE + 2);
            ulonglong2 ma = *(const ulonglong2*)(mb + b * SM_STRIDE);
            ulonglong2 mc = *(const ulonglong2*)(mb + b * SM_STRIDE + 2);
            u64 uv0 = ua.x, uv1 = ua.y, uv2 = uc.x, uv3 = uc.y;
            u64 m0 = ma.x, m1 = ma.y, m2 = mc.x, m3 = mc.y;
            FMA2(o[0][0], uv0, m0, o[0][0]);
            FMA2(o[0][1], uv0, m1, o[0][1]);
            FMA2(o[0][2], uv0, m2, o[0][2]);
            FMA2(o[0][3], uv0, m3, o[0][3]);
            FMA2(o[1][0], uv1, m0, o[1][0]);
            FMA2(o[1][1], uv1, m1, o[1][1]);
            FMA2(o[1][2], uv1, m2, o[1][2]);
            FMA2(o[1][3], uv1, m3, o[1][3]);
            FMA2(o[2][0], uv2, m0, o[2][0]);
            FMA2(o[2][1], uv2, m1, o[2][1]);
            FMA2(o[2][2], uv2, m2, o[2][2]);
            FMA2(o[2][3], uv2, m3, o[2][3]);
            FMA2(o[3][0], uv3, m0, o[3][0]);
            FMA2(o[3][1], uv3, m1, o[3][1]);
            FMA2(o[3][2], uv3, m2, o[3][2]);
            FMA2(o[3][3], uv3, m3, o[3][3]);
        }
    }

    // ---- Store partials: rows 8*ty + 2*j (+lane), dims 4*tx .. +3 ----
    {
        float* pbase = g_part + ((size_t)g * N_ROWS + (size_t)bx * ROWS_T) * D_DIM;
        #pragma unroll
        for (int j = 0; j < 4; ++j) {
            float4 lo, hi;
            UNPACK2(lo.x, hi.x, o[j][0]);
            UNPACK2(lo.y, hi.y, o[j][1]);
            UNPACK2(lo.z, hi.z, o[j][2]);
            UNPACK2(lo.w, hi.w, o[j][3]);
            int row = 8 * ty + 2 * j;
            *(float4*)(pbase + (size_t)row * D_DIM + 4 * tx)       = lo;
            *(float4*)(pbase + (size_t)(row + 1) * D_DIM + 4 * tx) = hi;
        }
    }
}

// ---------------------------------------------------------------------------
// Reduce NG partial buffers into the output (vectorized).
// ---------------------------------------------------------------------------
__global__ void reduce_kernel(float4* __restrict__ out) {
    int idx = blockIdx.x * blockDim.x + threadIdx.x;   // < N*D/4 = 131072
    const float4* p = (const float4*)g_part;
    float4 s = p[idx];
    #pragma unroll
    for (int g = 1; g < NG; ++g) {
        float4 v = p[(size_t)g * (N_ROWS * D_DIM / 4) + idx];
        s.x += v.x; s.y += v.y; s.z += v.z; s.w += v.w;
    }
    out[idx] = s;
}

// ---------------------------------------------------------------------------
extern "C" void kernel_launch(void* const* d_in, const int* in_sizes, int n_in,
                              void* d_out, int out_size) {
    const float* x   = nullptr;
    const float* eps = nullptr;
    const float* lam = nullptr;
    const float* eta = nullptr;
    const float* w   = nullptr;
    int ones_seen = 0;
    for (int i = 0; i < n_in; ++i) {
        int sz = in_sizes[i];
        const float* p = (const float*)d_in[i];
        if      (sz == N_ROWS * D_DIM)     x   = p;
        else if (sz == 2 * B_HALF * D_DIM) eps = p;
        else if (sz == D_DIM)              lam = p;
        else if (sz == 4 * B_HALF)         w   = p;
        else if (sz == 1) {
            if (ones_seen == 1) eta = p;   // second size-1 input is eta
            ones_seen++;
        }
    }

    cudaFuncSetAttribute(main_kernel,
                         cudaFuncAttributeMaxDynamicSharedMemorySize, SMEM_BYTES);

    main_kernel<<<dim3(N_ROWS / ROWS_T, NG), TB, SMEM_BYTES>>>(x, eps, lam, eta, w);
    reduce_kernel<<<(N_ROWS * D_DIM / 4 + 255) / 256, 256>>>((float4*)d_out);
}

// round 8
// speedup vs baseline: 1.5885x; 1.5885x over previous
#include <cuda_runtime.h>
#include <cstdint>

// Problem constants
#define N_ROWS 8192
#define D_DIM  64
#define B_HALF 1024          // epsilon = [tmp; -tmp] antisymmetry folds B=2048 -> 1024
#define TWO_PI 6.283185307179586f

// Tiling
#define TB      256          // threads per block
#define ROWS_T  128          // rows per block
#define BT      64           // basis per block
#define NG      (B_HALF / BT)   // 16 b-groups

// Shared layout (R3-proven: scalar tiles, in-register splats)
#define SX_STRIDE 132        // floats per k-row of x tile
#define SS_STRIDE 68         // floats per k-row of s tile
#define SM_STRIDE 68         // floats per b-row of M tile (alias of s region)
#define SU_STRIDE 65         // u64 per b-row of U tile (alias of x region)
#define OFF_X  0
#define OFF_S  (64 * SX_STRIDE * 4)                 // 33792
#define OFF_W  (OFF_S + 64 * SS_STRIDE * 4)         // 51200
#define SMEM_BYTES (OFF_W + 3 * 64 * 4)             // ws/wc/rlam = 51392

typedef unsigned long long u64;

// Packed f32x2 math (Blackwell FFMA2 — full-rate fp32, 2 FMAs per instruction)
#define FMA2(d, a, b, c) asm("fma.rn.f32x2 %0, %1, %2, %3;" : "=l"(d) : "l"(a), "l"(b), "l"(c))
#define PACK2(d, lo, hi) asm("mov.b64 %0, {%1, %2};"        : "=l"(d) : "f"(lo), "f"(hi))
#define UNPACK2(lo, hi, s) asm("mov.b64 {%0, %1}, %2;"      : "=f"(lo), "=f"(hi) : "l"(s))

// Device scratch
__device__ float g_part[NG * N_ROWS * D_DIM];   // 32 MB partials

// ---------------------------------------------------------------------------
// Fused kernel (R3 structure + in-block prep):
//   Stage 0: rlam, effective weights
//   Stage 1: x tile transposed; S tile = eps * rlam, transposed
//   Phase A: sim = X.S^T (register-tiled, FFMA2)  -> epilogue sin/cos -> U
//   Stage 2: U tile -> x-region alias; M tile derived from eps (L2) -> s-region
//   Phase B: f_partial = U @ M (register-tiled, FFMA2)
// Thread (ty = tid/16, tx = tid%16):
//   Phase A: 8 rows (4 rowpairs) x 4 basis (b = 4tx..+3)
//   Phase B: 8 rows x 4 dims (d = 4tx..+3), K = 64 basis
// ---------------------------------------------------------------------------
__global__ void __launch_bounds__(TB, 3)
main_kernel(const float* __restrict__ x,
            const float* __restrict__ eps,
            const float* __restrict__ lam,
            const float* __restrict__ eta,
            const float* __restrict__ w) {
    extern __shared__ char smem[];
    float* sXf = (float*)(smem + OFF_X);   // [64 k][SX_STRIDE]  x transposed
    float* sSf = (float*)(smem + OFF_S);   // [64 k][SS_STRIDE]  s transposed
    float* sWs = (float*)(smem + OFF_W);   // [64]
    float* sWc = sWs + 64;                 // [64]
    float* sRl = sWc + 64;                 // [64] 1/(2*pi*lam)
    u64*   sUu = (u64*)(smem + OFF_X);     // alias: [64 b][SU_STRIDE] U rowpairs
    float* sMf = (float*)(smem + OFF_S);   // alias: [64 b][SM_STRIDE] M tile

    const int tid = threadIdx.x;
    const int ty  = tid >> 4;              // 0..15
    const int tx  = tid & 15;              // 0..15
    const int bx  = blockIdx.x;
    const int g   = blockIdx.y;
    const int b0  = g * BT;

    // ---- Stage 0: rlam + effective weights ----
    if (tid < 64) {
        sRl[tid] = 1.0f / (TWO_PI * lam[tid]);
    } else if (tid < 128) {
        int b = tid - 64;
        sWs[b] = -(w[b0 + b] + w[b0 + b + B_HALF]);
    } else if (tid < 192) {
        int b = tid - 128;
        sWc[b] = w[2 * B_HALF + b0 + b] - w[3 * B_HALF + b0 + b];
    }
    __syncthreads();

    // ---- Stage 1: x tile transposed + S tile (s = eps * rlam), transposed ----
    {
        const float4* xg = (const float4*)(x + (size_t)bx * ROWS_T * D_DIM);
        #pragma unroll
        for (int it = 0; it < 8; ++it) {
            int i  = tid + it * TB;        // float4 id, 2048 total
            int r  = i >> 4;
            int k4 = (i & 15) * 4;
            float4 v = xg[i];
            sXf[(k4 + 0) * SX_STRIDE + r] = v.x;
            sXf[(k4 + 1) * SX_STRIDE + r] = v.y;
            sXf[(k4 + 2) * SX_STRIDE + r] = v.z;
            sXf[(k4 + 3) * SX_STRIDE + r] = v.w;
        }
        const float4* eg  = (const float4*)(eps + (size_t)b0 * D_DIM);
        const float4* rl4 = (const float4*)sRl;
        #pragma unroll
        for (int it = 0; it < 4; ++it) {
            int i  = tid + it * TB;        // float4 id, 1024 total
            int b  = i >> 4;
            int k4 = (i & 15) * 4;
            float4 e = eg[i];
            float4 r = rl4[i & 15];
            sSf[(k4 + 0) * SS_STRIDE + b] = e.x * r.x;
            sSf[(k4 + 1) * SS_STRIDE + b] = e.y * r.y;
            sSf[(k4 + 2) * SS_STRIDE + b] = e.z * r.z;
            sSf[(k4 + 3) * SS_STRIDE + b] = e.w * r.w;
        }
    }
    __syncthreads();

    // ---- Phase A: sim tile, rows packed 2/u64. acc[i=b_local][j=rowpair] ----
    u64 acc[4][4];
    #pragma unroll
    for (int i = 0; i < 4; ++i)
        #pragma unroll
        for (int j = 0; j < 4; ++j) acc[i][j] = 0ull;

    {
        const float* xbase = sXf + 8 * ty;       // rows 8*ty .. 8*ty+7
        const float* sbase = sSf + 4 * tx;       // basis 4*tx .. +3
        #pragma unroll 2
        for (int k = 0; k < 64; ++k) {
            const float4* xr = (const float4*)(xbase + k * SX_STRIDE);
            float4 xa = xr[0];
            float4 xb = xr[1];
            u64 xv0, xv1, xv2, xv3;
            PACK2(xv0, xa.x, xa.y);
            PACK2(xv1, xa.z, xa.w);
            PACK2(xv2, xb.x, xb.y);
            PACK2(xv3, xb.z, xb.w);
            float4 sv = *(const float4*)(sbase + k * SS_STRIDE);
            u64 s0, s1, s2, s3;
            PACK2(s0, sv.x, sv.x);
            PACK2(s1, sv.y, sv.y);
            PACK2(s2, sv.z, sv.z);
            PACK2(s3, sv.w, sv.w);
            FMA2(acc[0][0], xv0, s0, acc[0][0]);
            FMA2(acc[0][1], xv1, s0, acc[0][1]);
            FMA2(acc[0][2], xv2, s0, acc[0][2]);
            FMA2(acc[0][3], xv3, s0, acc[0][3]);
            FMA2(acc[1][0], xv0, s1, acc[1][0]);
            FMA2(acc[1][1], xv1, s1, acc[1][1]);
            FMA2(acc[1][2], xv2, s1, acc[1][2]);
            FMA2(acc[1][3], xv3, s1, acc[1][3]);
            FMA2(acc[2][0], xv0, s2, acc[2][0]);
            FMA2(acc[2][1], xv1, s2, acc[2][1]);
            FMA2(acc[2][2], xv2, s2, acc[2][2]);
            FMA2(acc[2][3], xv3, s2, acc[2][3]);
            FMA2(acc[3][0], xv0, s3, acc[3][0]);
            FMA2(acc[3][1], xv1, s3, acc[3][1]);
            FMA2(acc[3][2], xv2, s3, acc[3][2]);
            FMA2(acc[3][3], xv3, s3, acc[3][3]);
        }
    }

    // ---- Epilogue: acc (sim/2pi) -> u = sin*ws + cos*wc, in registers ----
    #pragma unroll
    for (int i = 0; i < 4; ++i) {
        int bl = tx * 4 + i;
        float ws = sWs[bl];
        float wc = sWc[bl];
        #pragma unroll
        for (int j = 0; j < 4; ++j) {
            float p0, p1;
            UNPACK2(p0, p1, acc[i][j]);
            float r0 = p0 - rintf(p0);
            float r1 = p1 - rintf(p1);
            float t0 = r0 * TWO_PI;
            float t1 = r1 * TWO_PI;
            float u0 = __sinf(t0) * ws + __cosf(t0) * wc;
            float u1 = __sinf(t1) * ws + __cosf(t1) * wc;
            PACK2(acc[i][j], u0, u1);
        }
    }

    // All shared reads of sXf/sSf done by every warp before aliasing
    __syncthreads();

    // ---- Stage 2: write U tile (rowpair-packed) into x-region;
    //      stage M tile into s-region, derived from eps (L2-resident):
    //      M[b][d<32]  =  2pi * eps[b][32+d] * rlam[32+d]
    //      M[b][d>=32] = -2pi * eps[b][d-32] * rlam[d-32]
    //                    -2pi*eta^2 * eps[b][d] * rlam[d]
    #pragma unroll
    for (int i = 0; i < 4; ++i) {
        int bl = tx * 4 + i;
        #pragma unroll
        for (int j = 0; j < 4; ++j) {
            sUu[bl * SU_STRIDE + ty * 4 + j] = acc[i][j];
        }
    }
    {
        const float4* eg  = (const float4*)(eps + (size_t)b0 * D_DIM);
        const float4* rl4 = (const float4*)sRl;
        float ev   = eta[0];
        float cEta = -TWO_PI * ev * ev;
        #pragma unroll
        for (int it = 0; it < 4; ++it) {
            int i = tid + it * TB;         // float4 id, 1024 total
            int b = i >> 4;
            int q = i & 15;                // dim-quad: dims 4q..4q+3
            float4 m;
            if (q < 8) {
                float4 e = eg[b * 16 + q + 8];
                float4 r = rl4[q + 8];
                m.x = TWO_PI * e.x * r.x;
                m.y = TWO_PI * e.y * r.y;
                m.z = TWO_PI * e.z * r.z;
                m.w = TWO_PI * e.w * r.w;
            } else {
                float4 e1 = eg[b * 16 + q - 8];
                float4 r1 = rl4[q - 8];
                float4 e2 = eg[b * 16 + q];
                float4 r2 = rl4[q];
                m.x = -TWO_PI * e1.x * r1.x + cEta * e2.x * r2.x;
                m.y = -TWO_PI * e1.y * r1.y + cEta * e2.y * r2.y;
                m.z = -TWO_PI * e1.z * r1.z + cEta * e2.z * r2.z;
                m.w = -TWO_PI * e1.w * r1.w + cEta * e2.w * r2.w;
            }
            *(float4*)(sMf + b * SM_STRIDE + 4 * q) = m;
        }
    }
    __syncthreads();

    // ---- Phase B: f_partial = U @ M.  o[j=rowpair][i=d_local] ----
    u64 o[4][4];
    #pragma unroll
    for (int j = 0; j < 4; ++j)
        #pragma unroll
        for (int i = 0; i < 4; ++i) o[j][i] = 0ull;

    {
        const u64*   ubase = sUu + 4 * ty;
        const float* mbase = sMf + 4 * tx;
        #pragma unroll 2
        for (int b = 0; b < 64; ++b) {
            u64 uv0 = ubase[b * SU_STRIDE + 0];
            u64 uv1 = ubase[b * SU_STRIDE + 1];
            u64 uv2 = ubase[b * SU_STRIDE + 2];
            u64 uv3 = ubase[b * SU_STRIDE + 3];
            float4 mv = *(const float4*)(mbase + b * SM_STRIDE);
            u64 m0, m1, m2, m3;
            PACK2(m0, mv.x, mv.x);
            PACK2(m1, mv.y, mv.y);
            PACK2(m2, mv.z, mv.z);
            PACK2(m3, mv.w, mv.w);
            FMA2(o[0][0], uv0, m0, o[0][0]);
            FMA2(o[0][1], uv0, m1, o[0][1]);
            FMA2(o[0][2], uv0, m2, o[0][2]);
            FMA2(o[0][3], uv0, m3, o[0][3]);
            FMA2(o[1][0], uv1, m0, o[1][0]);
            FMA2(o[1][1], uv1, m1, o[1][1]);
            FMA2(o[1][2], uv1, m2, o[1][2]);
            FMA2(o[1][3], uv1, m3, o[1][3]);
            FMA2(o[2][0], uv2, m0, o[2][0]);
            FMA2(o[2][1], uv2, m1, o[2][1]);
            FMA2(o[2][2], uv2, m2, o[2][2]);
            FMA2(o[2][3], uv2, m3, o[2][3]);
            FMA2(o[3][0], uv3, m0, o[3][0]);
            FMA2(o[3][1], uv3, m1, o[3][1]);
            FMA2(o[3][2], uv3, m2, o[3][2]);
            FMA2(o[3][3], uv3, m3, o[3][3]);
        }
    }

    // ---- Store partials: rows 8*ty + 2*j (+lane), dims 4*tx .. +3 ----
    {
        float* pbase = g_part + ((size_t)g * N_ROWS + (size_t)bx * ROWS_T) * D_DIM;
        #pragma unroll
        for (int j = 0; j < 4; ++j) {
            float4 lo, hi;
            UNPACK2(lo.x, hi.x, o[j][0]);
            UNPACK2(lo.y, hi.y, o[j][1]);
            UNPACK2(lo.z, hi.z, o[j][2]);
            UNPACK2(lo.w, hi.w, o[j][3]);
            int row = 8 * ty + 2 * j;
            *(float4*)(pbase + (size_t)row * D_DIM + 4 * tx)       = lo;
            *(float4*)(pbase + (size_t)(row + 1) * D_DIM + 4 * tx) = hi;
        }
    }
}

// ---------------------------------------------------------------------------
// Reduce NG partial buffers into the output. Explicit register staging for
// MLP=16 (prior version was dependence-throttled at regs=32, 43% DRAM).
// ---------------------------------------------------------------------------
__global__ void reduce_kernel(float4* __restrict__ out) {
    int idx = blockIdx.x * blockDim.x + threadIdx.x;   // < N*D/4 = 131072
    const float4* p = (const float4*)g_part;
    float4 v[NG];
    #pragma unroll
    for (int g = 0; g < NG; ++g) {
        v[g] = p[(size_t)g * (N_ROWS * D_DIM / 4) + idx];
    }
    #pragma unroll
    for (int s = NG / 2; s > 0; s >>= 1) {
        #pragma unroll
        for (int g = 0; g < s; ++g) {
            v[g].x += v[g + s].x;
            v[g].y += v[g + s].y;
            v[g].z += v[g + s].z;
            v[g].w += v[g + s].w;
        }
    }
    out[idx] = v[0];
}

// ---------------------------------------------------------------------------
extern "C" void kernel_launch(void* const* d_in, const int* in_sizes, int n_in,
                              void* d_out, int out_size) {
    const float* x   = nullptr;
    const float* eps = nullptr;
    const float* lam = nullptr;
    const float* eta = nullptr;
    const float* w   = nullptr;
    int ones_seen = 0;
    for (int i = 0; i < n_in; ++i) {
        int sz = in_sizes[i];
        const float* p = (const float*)d_in[i];
        if      (sz == N_ROWS * D_DIM)     x   = p;
        else if (sz == 2 * B_HALF * D_DIM) eps = p;
        else if (sz == D_DIM)              lam = p;
        else if (sz == 4 * B_HALF)         w   = p;
        else if (sz == 1) {
            if (ones_seen == 1) eta = p;   // second size-1 input is eta
            ones_seen++;
        }
    }

    cudaFuncSetAttribute(main_kernel,
                         cudaFuncAttributeMaxDynamicSharedMemorySize, SMEM_BYTES);

    main_kernel<<<dim3(N_ROWS / ROWS_T, NG), TB, SMEM_BYTES>>>(x, eps, lam, eta, w);
    reduce_kernel<<<(N_ROWS * D_DIM / 4 + 255) / 256, 256>>>((float4*)d_out);
}

// round 9
// speedup vs baseline: 1.7628x; 1.1097x over previous
#include <cuda_runtime.h>
#include <cstdint>

// Problem constants
#define N_ROWS 8192
#define D_DIM  64
#define B_HALF 1024          // epsilon = [tmp; -tmp] antisymmetry folds B=2048 -> 1024
#define TWO_PI 6.283185307179586f

// Tiling
#define TB 128               // threads per block == rows per block... (prep only uses 256)
#define TBM 256              // main threads per block
#define ROWS_T 128           // rows per block
#define BT 64                // basis per block
#define NG (B_HALF / BT)     // 16 b-groups

// Shared layout (R3-proven: scalar tiles, in-register splats)
#define SX_STRIDE 132        // floats per k-row of x tile
#define SS_STRIDE 68         // floats per k-row of s tile
#define SU_STRIDE 65         // u64 per b-row of U tile (alias of x region)
#define OFF_X  0
#define OFF_S  (64 * SX_STRIDE * 4)                 // 33792
#define OFF_W  (OFF_S + 64 * SS_STRIDE * 4)         // 51200
#define SMEM_BYTES (OFF_W + 2 * BT * 4)             // 51712

typedef unsigned long long u64;

// Packed f32x2 math (Blackwell FFMA2)
#define FMA2(d, a, b, c) asm("fma.rn.f32x2 %0, %1, %2, %3;" : "=l"(d) : "l"(a), "l"(b), "l"(c))
#define PACK2(d, lo, hi) asm("mov.b64 %0, {%1, %2};"        : "=l"(d) : "f"(lo), "f"(hi))
#define UNPACK2(lo, hi, s) asm("mov.b64 {%0, %1}, %2;"      : "=f"(lo), "=f"(hi) : "l"(s))

// Vector float atomic-add, no return (REDG.128). sm_90+.
#define RED_ADD_V4(ptr, a, b, c, d) \
    asm volatile("red.global.add.v4.f32 [%0], {%1, %2, %3, %4};" \
                 :: "l"(ptr), "f"(a), "f"(b), "f"(c), "f"(d) : "memory")

// Device scratch
__device__ float g_S[B_HALF * D_DIM];     // s[b][j] = eps[b][j] / (2*pi*lam[j])
__device__ float g_M[B_HALF * D_DIM];     // mat[b][i]
__device__ float g_ws[B_HALF];            // -(w_s[b] + w_s[b+1024])
__device__ float g_wc[B_HALF];            //  (w_c[b] - w_c[b+1024])

// ---------------------------------------------------------------------------
// Precompute S, mat, effective weights; also zero the output (it accumulates
// via red.global.add in main). 256 blocks x 256 threads.
// ---------------------------------------------------------------------------
__global__ void prep_kernel(const float* __restrict__ eps,
                            const float* __restrict__ lam,
                            const float* __restrict__ eta,
                            const float* __restrict__ w,
                            float4* __restrict__ out) {
    int idx = blockIdx.x * blockDim.x + threadIdx.x;
    if (idx < B_HALF * D_DIM) {
        int b = idx >> 6;
        int j = idx & 63;
        float l = lam[j];
        g_S[idx] = eps[idx] / (TWO_PI * l);
        float eta2 = eta[0] * eta[0];
        float m;
        if (j < 32) {
            m = eps[b * 64 + 32 + j] / lam[32 + j];
        } else {
            m = -eps[b * 64 + (j - 32)] / lam[j - 32] - eta2 * eps[idx] / l;
        }
        g_M[idx] = m;
    }
    if (idx < B_HALF) {
        g_ws[idx] = -(w[idx] + w[idx + B_HALF]);
        g_wc[idx] = w[2 * B_HALF + idx] - w[3 * B_HALF + idx];
    }
    // Zero output: 131072 float4 across 65536 threads -> 2 each
    out[idx]         = make_float4(0.f, 0.f, 0.f, 0.f);
    out[idx + 65536] = make_float4(0.f, 0.f, 0.f, 0.f);
}

// ---------------------------------------------------------------------------
// Main fused kernel (exact R3/R5 measured-best structure; only the final
// store is changed from g_part writes to red.global.add into d_out).
// Thread (ty = tid/16, tx = tid%16):
//   Phase A: 8 rows (4 rowpairs) x 4 basis (b = 4tx..+3)
//   Phase B: 8 rows x 4 dims (d = 4tx..+3), K = 64 basis of this group
// ---------------------------------------------------------------------------
__global__ void __launch_bounds__(TBM, 3)
main_kernel(const float* __restrict__ x, float* __restrict__ out) {
    extern __shared__ char smem[];
    float* sXf = (float*)(smem + OFF_X);   // [64 k][SX_STRIDE]  x transposed
    float* sSf = (float*)(smem + OFF_S);   // [64 k][SS_STRIDE]  s transposed
    float* sW  = (float*)(smem + OFF_W);   // [2*BT] interleaved ws/wc
    u64*   sUu = (u64*)(smem + OFF_X);     // alias: [64 b][SU_STRIDE] U rowpairs
    float* sMf = (float*)(smem + OFF_S);   // alias: [64 b][64] M tile

    const int tid = threadIdx.x;
    const int ty  = tid >> 4;              // 0..15
    const int tx  = tid & 15;              // 0..15
    const int bx  = blockIdx.x;
    const int g   = blockIdx.y;
    const int b0  = g * BT;

    // ---- Stage x/s tiles transposed into shared memory ----
    {
        const float4* xg = (const float4*)(x + (size_t)bx * ROWS_T * D_DIM);
        #pragma unroll
        for (int it = 0; it < 8; ++it) {
            int i  = tid + it * TBM;       // float4 id, 2048 total
            int r  = i >> 4;
            int k4 = (i & 15) * 4;
            float4 v = xg[i];
            sXf[(k4 + 0) * SX_STRIDE + r] = v.x;
            sXf[(k4 + 1) * SX_STRIDE + r] = v.y;
            sXf[(k4 + 2) * SX_STRIDE + r] = v.z;
            sXf[(k4 + 3) * SX_STRIDE + r] = v.w;
        }
        const float4* sg = (const float4*)(g_S + (size_t)b0 * D_DIM);
        #pragma unroll
        for (int it = 0; it < 4; ++it) {
            int i  = tid + it * TBM;       // float4 id, 1024 total
            int b  = i >> 4;
            int k4 = (i & 15) * 4;
            float4 v = sg[i];
            sSf[(k4 + 0) * SS_STRIDE + b] = v.x;
            sSf[(k4 + 1) * SS_STRIDE + b] = v.y;
            sSf[(k4 + 2) * SS_STRIDE + b] = v.z;
            sSf[(k4 + 3) * SS_STRIDE + b] = v.w;
        }
        if (tid < BT) {
            sW[2 * tid]     = g_ws[b0 + tid];
            sW[2 * tid + 1] = g_wc[b0 + tid];
        }
    }
    __syncthreads();

    // ---- Phase A: sim tile, rows packed 2/u64. acc[i=b_local][j=rowpair] ----
    u64 acc[4][4];
    #pragma unroll
    for (int i = 0; i < 4; ++i)
        #pragma unroll
        for (int j = 0; j < 4; ++j) acc[i][j] = 0ull;

    {
        const float* xbase = sXf + 8 * ty;       // rows 8*ty .. 8*ty+7
        const float* sbase = sSf + 4 * tx;       // basis 4*tx .. +3
        #pragma unroll 2
        for (int k = 0; k < 64; ++k) {
            const float4* xr = (const float4*)(xbase + k * SX_STRIDE);
            float4 xa = xr[0];
            float4 xb = xr[1];
            u64 xv0, xv1, xv2, xv3;
            PACK2(xv0, xa.x, xa.y);
            PACK2(xv1, xa.z, xa.w);
            PACK2(xv2, xb.x, xb.y);
            PACK2(xv3, xb.z, xb.w);
            float4 sv = *(const float4*)(sbase + k * SS_STRIDE);
            u64 s0, s1, s2, s3;
            PACK2(s0, sv.x, sv.x);
            PACK2(s1, sv.y, sv.y);
            PACK2(s2, sv.z, sv.z);
            PACK2(s3, sv.w, sv.w);
            FMA2(acc[0][0], xv0, s0, acc[0][0]);
            FMA2(acc[0][1], xv1, s0, acc[0][1]);
            FMA2(acc[0][2], xv2, s0, acc[0][2]);
            FMA2(acc[0][3], xv3, s0, acc[0][3]);
            FMA2(acc[1][0], xv0, s1, acc[1][0]);
            FMA2(acc[1][1], xv1, s1, acc[1][1]);
            FMA2(acc[1][2], xv2, s1, acc[1][2]);
            FMA2(acc[1][3], xv3, s1, acc[1][3]);
            FMA2(acc[2][0], xv0, s2, acc[2][0]);
            FMA2(acc[2][1], xv1, s2, acc[2][1]);
            FMA2(acc[2][2], xv2, s2, acc[2][2]);
            FMA2(acc[2][3], xv3, s2, acc[2][3]);
            FMA2(acc[3][0], xv0, s3, acc[3][0]);
            FMA2(acc[3][1], xv1, s3, acc[3][1]);
            FMA2(acc[3][2], xv2, s3, acc[3][2]);
            FMA2(acc[3][3], xv3, s3, acc[3][3]);
        }
    }

    // ---- Epilogue: acc (sim/2pi) -> u = sin*ws + cos*wc ----
    #pragma unroll
    for (int i = 0; i < 4; ++i) {
        int bl = tx * 4 + i;
        float ws = sW[2 * bl];
        float wc = sW[2 * bl + 1];
        #pragma unroll
        for (int j = 0; j < 4; ++j) {
            float p0, p1;
            UNPACK2(p0, p1, acc[i][j]);
            float r0 = p0 - rintf(p0);
            float r1 = p1 - rintf(p1);
            float t0 = r0 * TWO_PI;
            float t1 = r1 * TWO_PI;
            float u0 = __sinf(t0) * ws + __cosf(t0) * wc;
            float u1 = __sinf(t1) * ws + __cosf(t1) * wc;
            PACK2(acc[i][j], u0, u1);
        }
    }

    __syncthreads();   // all shared reads of sXf/sSf done before aliasing

    // ---- Write U tile (rowpair-packed) + stage M tile into aliased smem ----
    #pragma unroll
    for (int i = 0; i < 4; ++i) {
        int bl = tx * 4 + i;
        #pragma unroll
        for (int j = 0; j < 4; ++j) {
            sUu[bl * SU_STRIDE + ty * 4 + j] = acc[i][j];
        }
    }
    {
        const float4* mg = (const float4*)(g_M + (size_t)b0 * D_DIM);
        float4* md = (float4*)sMf;
        #pragma unroll
        for (int it = 0; it < 4; ++it) {
            int i = tid + it * TBM;
            md[i] = mg[i];
        }
    }
    __syncthreads();

    // ---- Phase B: f_partial = U @ M.  o[j=rowpair][i=d_local] ----
    u64 o[4][4];
    #pragma unroll
    for (int j = 0; j < 4; ++j)
        #pragma unroll
        for (int i = 0; i < 4; ++i) o[j][i] = 0ull;

    {
        const u64*   ubase = sUu + 4 * ty;
        const float* mbase = sMf + 4 * tx;
        #pragma unroll 2
        for (int b = 0; b < 64; ++b) {
            u64 uv0 = ubase[b * SU_STRIDE + 0];
            u64 uv1 = ubase[b * SU_STRIDE + 1];
            u64 uv2 = ubase[b * SU_STRIDE + 2];
            u64 uv3 = ubase[b * SU_STRIDE + 3];
            float4 mv = *(const float4*)(mbase + b * 64);
            u64 m0, m1, m2, m3;
            PACK2(m0, mv.x, mv.x);
            PACK2(m1, mv.y, mv.y);
            PACK2(m2, mv.z, mv.z);
            PACK2(m3, mv.w, mv.w);
            FMA2(o[0][0], uv0, m0, o[0][0]);
            FMA2(o[0][1], uv0, m1, o[0][1]);
            FMA2(o[0][2], uv0, m2, o[0][2]);
            FMA2(o[0][3], uv0, m3, o[0][3]);
            FMA2(o[1][0], uv1, m0, o[1][0]);
            FMA2(o[1][1], uv1, m1, o[1][1]);
            FMA2(o[1][2], uv1, m2, o[1][2]);
            FMA2(o[1][3], uv1, m3, o[1][3]);
            FMA2(o[2][0], uv2, m0, o[2][0]);
            FMA2(o[2][1], uv2, m1, o[2][1]);
            FMA2(o[2][2], uv2, m2, o[2][2]);
            FMA2(o[2][3], uv2, m3, o[2][3]);
            FMA2(o[3][0], uv3, m0, o[3][0]);
            FMA2(o[3][1], uv3, m1, o[3][1]);
            FMA2(o[3][2], uv3, m2, o[3][2]);
            FMA2(o[3][3], uv3, m3, o[3][3]);
        }
    }

    // ---- Accumulate directly into output via vector REDG (no partials) ----
    {
        float* obase = out + (size_t)bx * ROWS_T * D_DIM;
        #pragma unroll
        for (int j = 0; j < 4; ++j) {
            float4 lo, hi;
            UNPACK2(lo.x, hi.x, o[j][0]);
            UNPACK2(lo.y, hi.y, o[j][1]);
            UNPACK2(lo.z, hi.z, o[j][2]);
            UNPACK2(lo.w, hi.w, o[j][3]);
            int row = 8 * ty + 2 * j;
            float* p0 = obase + (size_t)row * D_DIM + 4 * tx;
            float* p1 = obase + (size_t)(row + 1) * D_DIM + 4 * tx;
            RED_ADD_V4(p0, lo.x, lo.y, lo.z, lo.w);
            RED_ADD_V4(p1, hi.x, hi.y, hi.z, hi.w);
        }
    }
}

// ---------------------------------------------------------------------------
extern "C" void kernel_launch(void* const* d_in, const int* in_sizes, int n_in,
                              void* d_out, int out_size) {
    const float* x   = nullptr;
    const float* eps = nullptr;
    const float* lam = nullptr;
    const float* eta = nullptr;
    const float* w   = nullptr;
    int ones_seen = 0;
    for (int i = 0; i < n_in; ++i) {
        int sz = in_sizes[i];
        const float* p = (const float*)d_in[i];
        if      (sz == N_ROWS * D_DIM)     x   = p;
        else if (sz == 2 * B_HALF * D_DIM) eps = p;
        else if (sz == D_DIM)              lam = p;
        else if (sz == 4 * B_HALF)         w   = p;
        else if (sz == 1) {
            if (ones_seen == 1) eta = p;   // second size-1 input is eta
            ones_seen++;
        }
    }

    cudaFuncSetAttribute(main_kernel,
                         cudaFuncAttributeMaxDynamicSharedMemorySize, SMEM_BYTES);

    prep_kernel<<<(B_HALF * D_DIM + 255) / 256, 256>>>(eps, lam, eta, w,
                                                       (float4*)d_out);
    main_kernel<<<dim3(N_ROWS / ROWS_T, NG), TBM, SMEM_BYTES>>>(x, (float*)d_out);
}